// round 1
// baseline (speedup 1.0000x reference)
#include <cuda_runtime.h>

typedef unsigned long long u64;

#define B_    16384
#define N_    128
#define L_    6
#define H_    64
#define DIR_  16
#define NBLK  2048
#define NTHR  128

// ---------- packed f32x2 helpers (FFMA2 path, PTX-only) ----------
static __device__ __forceinline__ u64 ffma2(u64 a, u64 b, u64 c) {
    u64 d;
    asm("fma.rn.f32x2 %0, %1, %2, %3;" : "=l"(d) : "l"(a), "l"(b), "l"(c));
    return d;
}
static __device__ __forceinline__ u64 pack2(float x) {
    u64 r; unsigned xi = __float_as_uint(x);
    asm("mov.b64 %0, {%1, %1};" : "=l"(r) : "r"(xi));
    return r;
}
static __device__ __forceinline__ u64 pack2f(float a, float b) {
    u64 r;
    asm("mov.b64 %0, {%1, %2};" : "=l"(r)
        : "r"(__float_as_uint(a)), "r"(__float_as_uint(b)));
    return r;
}
static __device__ __forceinline__ void unpack2(u64 v, float& a, float& b) {
    unsigned lo, hi;
    asm("mov.b64 {%0, %1}, %2;" : "=r"(lo), "=r"(hi) : "l"(v));
    a = __uint_as_float(lo); b = __uint_as_float(hi);
}

__global__ void __launch_bounds__(NTHR, 2)
surfnet_kernel(const int*    __restrict__ x,
               const float*  __restrict__ dirg,
               const float4* __restrict__ gw,
               const float*  __restrict__ W0, const float* __restrict__ b0,
               const float*  __restrict__ W1, const float* __restrict__ b1,
               const float*  __restrict__ W2, const float* __restrict__ b2,
               float* __restrict__ outSigma, float* __restrict__ outColor)
{
    __shared__ __align__(16) float sW0[34 * 64];
    __shared__ __align__(16) float sW1[64 * 64];
    __shared__ __align__(16) u64   sW2p[64];
    __shared__ float sW2z[64];
    __shared__ float sB0[64];
    __shared__ __align__(16) float sB1[64];
    __shared__ float sB2[3];
    __shared__ __align__(16) float sPre0[64];
    __shared__ float sSig[N_];
    __shared__ float sD[DIR_];
    __shared__ float sMaxRed[4];
    __shared__ float sCRed[12];

    const int tid  = threadIdx.x;
    const int lane = tid & 31;
    const int warp = tid >> 5;

    // ---- stage weights in shared (once per block) ----
    for (int i = tid; i < 34 * 64; i += NTHR) sW0[i] = W0[i];
    for (int i = tid; i < 64 * 64; i += NTHR) sW1[i] = W1[i];
    if (tid < 64) {
        sB0[tid] = b0[tid];
        sB1[tid] = b1[tid];
        float w2a = W2[tid * 3 + 0], w2b = W2[tid * 3 + 1], w2c = W2[tid * 3 + 2];
        sW2p[tid] = pack2f(w2a, w2b);
        sW2z[tid] = w2c;
    }
    if (tid < 3) sB2[tid] = b2[tid];
    __syncthreads();

    for (int row = blockIdx.x; row < B_; row += gridDim.x) {
        // direction vector for this batch row (shared across all 128 samples)
        if (tid < DIR_) sD[tid] = dirg[(size_t)row * DIR_ + tid];

        // ---- gather: 6 table rows per point ----
        const int2* xr = ((const int2*)x) + ((size_t)row * N_ + tid) * 3;
        int2 i01 = xr[0], i23 = xr[1], i45 = xr[2];
        float4 f0 = __ldg(gw + i01.x);
        float4 f1 = __ldg(gw + i01.y);
        float4 f2 = __ldg(gw + i23.x);
        float4 f3 = __ldg(gw + i23.y);
        float4 f4 = __ldg(gw + i45.x);
        float4 f5 = __ldg(gw + i45.y);

        float geo[18];
        geo[0]  = f0.y; geo[1]  = f0.z; geo[2]  = f0.w;
        geo[3]  = f1.y; geo[4]  = f1.z; geo[5]  = f1.w;
        geo[6]  = f2.y; geo[7]  = f2.z; geo[8]  = f2.w;
        geo[9]  = f3.y; geo[10] = f3.z; geo[11] = f3.w;
        geo[12] = f4.y; geo[13] = f4.z; geo[14] = f4.w;
        geo[15] = f5.y; geo[16] = f5.z; geo[17] = f5.w;

        float s = fminf(fmaxf(f0.x, 0.f), 1.f);
        s *= fminf(fmaxf(f1.x, 0.f), 1.f);
        s *= fminf(fmaxf(f2.x, 0.f), 1.f);
        s *= fminf(fmaxf(f3.x, 0.f), 1.f);
        s *= fminf(fmaxf(f4.x, 0.f), 1.f);
        s *= fminf(fmaxf(f5.x, 0.f), 1.f);
        float sigma0 = s + 1e-4f;

        // ---- row max (axis=1) ----
        float m = sigma0;
        #pragma unroll
        for (int o = 16; o > 0; o >>= 1)
            m = fmaxf(m, __shfl_xor_sync(0xffffffffu, m, o));
        if (lane == 0) sMaxRed[warp] = m;
        __syncthreads();  // sD, sMaxRed ready

        // pre0[j] = b0[j] + sum_k d[k]*W0[k][j]  (hoisted per-row half of layer 0)
        if (tid < 64) {
            float acc = sB0[tid];
            #pragma unroll
            for (int k = 0; k < DIR_; k++)
                acc = fmaf(sD[k], sW0[k * 64 + tid], acc);
            sPre0[tid] = acc;
        }

        float rowmax = fmaxf(fmaxf(sMaxRed[0], sMaxRed[1]),
                             fmaxf(sMaxRed[2], sMaxRed[3]));
        float sigma = sigma0 / rowmax;
        sSig[tid] = sigma;
        outSigma[(size_t)row * N_ + tid] = sigma;
        __syncthreads();  // sPre0, sSig ready

        float wgt = (tid == 0 ? 1.f : 1.f - sSig[tid - 1]) * sigma;

        // ---- layer 0 (geo half): 18 -> 64, packed f32x2 ----
        u64 acc[32];
        {
            const u64* pre = (const u64*)sPre0;
            #pragma unroll
            for (int p = 0; p < 32; p++) acc[p] = pre[p];
        }
        const float* w0g = sW0 + DIR_ * 64;
        #pragma unroll 6
        for (int k = 0; k < 18; k++) {
            u64 a = pack2(geo[k]);
            const ulonglong2* wr = (const ulonglong2*)(w0g + k * 64);
            #pragma unroll
            for (int j = 0; j < 16; j++) {
                ulonglong2 w = wr[j];
                acc[2 * j]     = ffma2(a, w.x, acc[2 * j]);
                acc[2 * j + 1] = ffma2(a, w.y, acc[2 * j + 1]);
            }
        }
        float act[64];
        #pragma unroll
        for (int p = 0; p < 32; p++) {
            float lo, hi; unpack2(acc[p], lo, hi);
            act[2 * p]     = fmaxf(lo, 0.f);
            act[2 * p + 1] = fmaxf(hi, 0.f);
        }

        // ---- layer 1: 64 -> 64 ----
        u64 acc1[32];
        {
            const u64* bb = (const u64*)sB1;
            #pragma unroll
            for (int p = 0; p < 32; p++) acc1[p] = bb[p];
        }
        #pragma unroll 4
        for (int k = 0; k < 64; k++) {
            u64 a = pack2(act[k]);
            const ulonglong2* wr = (const ulonglong2*)(sW1 + k * 64);
            #pragma unroll
            for (int j = 0; j < 16; j++) {
                ulonglong2 w = wr[j];
                acc1[2 * j]     = ffma2(a, w.x, acc1[2 * j]);
                acc1[2 * j + 1] = ffma2(a, w.y, acc1[2 * j + 1]);
            }
        }
        #pragma unroll
        for (int p = 0; p < 32; p++) {
            float lo, hi; unpack2(acc1[p], lo, hi);
            act[2 * p]     = fmaxf(lo, 0.f);
            act[2 * p + 1] = fmaxf(hi, 0.f);
        }

        // ---- layer 2: 64 -> 3 ----
        u64 accp = pack2f(sB2[0], sB2[1]);
        float c2 = sB2[2];
        #pragma unroll 8
        for (int k = 0; k < 64; k++) {
            float a = act[k];
            accp = ffma2(pack2(a), sW2p[k], accp);
            c2 = fmaf(a, sW2z[k], c2);
        }
        float c0, c1; unpack2(accp, c0, c1);
        c0 = 1.f / (1.f + __expf(-c0));
        c1 = 1.f / (1.f + __expf(-c1));
        c2 = 1.f / (1.f + __expf(-c2));

        // ---- weighted color sum over the 128 samples ----
        float r0 = wgt * c0, r1 = wgt * c1, r2 = wgt * c2;
        #pragma unroll
        for (int o = 16; o > 0; o >>= 1) {
            r0 += __shfl_xor_sync(0xffffffffu, r0, o);
            r1 += __shfl_xor_sync(0xffffffffu, r1, o);
            r2 += __shfl_xor_sync(0xffffffffu, r2, o);
        }
        if (lane == 0) {
            sCRed[warp * 3 + 0] = r0;
            sCRed[warp * 3 + 1] = r1;
            sCRed[warp * 3 + 2] = r2;
        }
        __syncthreads();  // sCRed ready; also fences row-local shared reuse
        if (tid == 0) {
            float t0 = sCRed[0] + sCRed[3] + sCRed[6] + sCRed[9];
            float t1 = sCRed[1] + sCRed[4] + sCRed[7] + sCRed[10];
            float t2 = sCRed[2] + sCRed[5] + sCRed[8] + sCRed[11];
            float* oc = outColor + (size_t)row * 3;
            oc[0] = t0; oc[1] = t1; oc[2] = t2;
        }
    }
}

extern "C" void kernel_launch(void* const* d_in, const int* in_sizes, int n_in,
                              void* d_out, int out_size)
{
    const int*    x    = (const int*)d_in[0];
    const float*  dirg = (const float*)d_in[1];
    const float4* gw   = (const float4*)d_in[2];
    const float*  W0   = (const float*)d_in[3];
    const float*  b0   = (const float*)d_in[4];
    const float*  W1   = (const float*)d_in[5];
    const float*  b1   = (const float*)d_in[6];
    const float*  W2   = (const float*)d_in[7];
    const float*  b2   = (const float*)d_in[8];

    float* outSigma = (float*)d_out;                       // (B, N, 1) flattened
    float* outColor = outSigma + (size_t)B_ * N_;          // (B, 3) flattened

    surfnet_kernel<<<NBLK, NTHR>>>(x, dirg, gw, W0, b0, W1, b1, W2, b2,
                                   outSigma, outColor);
}